// round 3
// baseline (speedup 1.0000x reference)
#include <cuda_runtime.h>
#include <math.h>

#define NQ 16
#define DIM 65536
#define BATCH 64
#define NC 23

__device__ float4 g_state4[BATCH * DIM / 2];   // 32 MB state
__device__ float2 g_U[2][BATCH][NQ][4];        // fused Rot@RX
__device__ float2 g_crx[2][NQ];                // (cos(th/2), sin(th/2))
__device__ float  g_partial[BATCH][8][16];

__device__ __forceinline__ float2 cmul(float2 a, float2 b) {
    return make_float2(a.x * b.x - a.y * b.y, a.x * b.y + a.y * b.x);
}
__device__ __forceinline__ void umix(float2& a0, float2& a1,
                                     float2 u0, float2 u1, float2 u2, float2 u3) {
    float2 n0, n1;
    n0.x = u0.x * a0.x - u0.y * a0.y + u1.x * a1.x - u1.y * a1.y;
    n0.y = u0.x * a0.y + u0.y * a0.x + u1.x * a1.y + u1.y * a1.x;
    n1.x = u2.x * a0.x - u2.y * a0.y + u3.x * a1.x - u3.y * a1.y;
    n1.y = u2.x * a0.y + u2.y * a0.x + u3.x * a1.y + u3.y * a1.x;
    a0 = n0; a1 = n1;
}
// RX pair mix (used when control bit = 1): RX=[[c,-is],[-is,c]]
__device__ __forceinline__ void crxmix(float2& a0, float2& a1, float c, float s) {
    float2 n0 = make_float2(c * a0.x + s * a1.y, c * a0.y - s * a1.x);
    float2 n1 = make_float2(s * a0.y + c * a1.x, -s * a0.x + c * a1.y);
    a0 = n0; a1 = n1;
}

// ---------------- P0: fused U = Rot @ RX, CRX tables ------------------------
__global__ void k_prep(const float* __restrict__ x, const float* __restrict__ w0,
                       const float* __restrict__ x0, const float* __restrict__ w1,
                       const float* __restrict__ x1) {
    int t = blockIdx.x * blockDim.x + threadIdx.x;
    if (t < 2 * NQ) {
        int l = t >> 4, q = t & 15;
        float th = 0.5f * (l == 0 ? x0[q] : x1[q]);
        g_crx[l][q] = make_float2(cosf(th), sinf(th));
    }
    if (t < 2 * BATCH * NQ) {
        int l = t / (BATCH * NQ);
        int r = t % (BATCH * NQ);
        int b = r / NQ, q = r % NQ;
        float hx = 0.5f * x[b * NQ + q];
        float cx = cosf(hx), sx = sinf(hx);
        const float* w = (l == 0 ? w0 : w1) + q * 3;
        float phi = w[0], th = w[1], om = w[2];
        float ct = cosf(0.5f * th), st = sinf(0.5f * th);
        float ap = 0.5f * (phi + om), am = 0.5f * (phi - om);
        float cap = cosf(ap), sap = sinf(ap), cam = cosf(am), sam = sinf(am);
        float2 a  = make_float2(cap * ct, -sap * ct);
        float2 bb = make_float2(-cam * st, -sam * st);
        float2 cc = make_float2(cam * st, -sam * st);
        float2 d  = make_float2(cap * ct,  sap * ct);
        g_U[l][b][q][0] = make_float2(a.x * cx + bb.y * sx,  a.y * cx - bb.x * sx);
        g_U[l][b][q][1] = make_float2(a.y * sx + bb.x * cx, -a.x * sx + bb.y * cx);
        g_U[l][b][q][2] = make_float2(cc.x * cx + d.y * sx,  cc.y * cx - d.x * sx);
        g_U[l][b][q][3] = make_float2(cc.y * sx + d.x * cx, -cc.x * sx + d.y * cx);
    }
}

// ---------------- P1: product state + L1 CRX(b15->b14), CRX(b14->b13) -------
__global__ void k_init() {
    int b = blockIdx.y;
    int t = blockIdx.x * blockDim.x + threadIdx.x;   // 0..8191 : bits 0..12
    __shared__ float2 f[16][2];
    if (threadIdx.x < 32) {
        int j = threadIdx.x >> 1, v = threadIdx.x & 1;
        f[j][v] = g_U[0][b][15 - j][v * 2];          // column 0 of U, wire 15-j
    }
    __syncthreads();
    float2 c = f[0][t & 1];
    #pragma unroll
    for (int j = 1; j <= 12; j++) c = cmul(c, f[j][(t >> j) & 1]);
    float2 a[2][2][2];   // [b15][b14][b13]
    float2 a130 = cmul(c, f[13][0]), a131 = cmul(c, f[13][1]);
    #pragma unroll
    for (int b14 = 0; b14 < 2; b14++) {
        float2 v0 = cmul(a130, f[14][b14]);
        float2 v1 = cmul(a131, f[14][b14]);
        a[0][b14][0] = cmul(v0, f[15][0]); a[1][b14][0] = cmul(v0, f[15][1]);
        a[0][b14][1] = cmul(v1, f[15][0]); a[1][b14][1] = cmul(v1, f[15][1]);
    }
    float2 cs = g_crx[0][0];                          // ctrl b15 -> tgt b14
    crxmix(a[1][0][0], a[1][1][0], cs.x, cs.y);
    crxmix(a[1][0][1], a[1][1][1], cs.x, cs.y);
    cs = g_crx[0][1];                                 // ctrl b14 -> tgt b13
    crxmix(a[0][1][0], a[0][1][1], cs.x, cs.y);
    crxmix(a[1][1][0], a[1][1][1], cs.x, cs.y);
    float2* st = (float2*)g_state4 + (size_t)b * DIM;
    #pragma unroll
    for (int b15 = 0; b15 < 2; b15++)
        #pragma unroll
        for (int b14 = 0; b14 < 2; b14++)
            #pragma unroll
            for (int b13 = 0; b13 < 2; b13++)
                st[t | (b13 << 13) | (b14 << 14) | (b15 << 15)] = a[b15][b14][b13];
}

// ---------------- P2/P4: smem chunk (bits 0..13), adjacent-CRX chain --------
__global__ __launch_bounds__(512) void k_chain(int layer) {
    extern __shared__ float2 s[];
    int b = blockIdx.y, tid = threadIdx.x;
    float4* g4 = g_state4 + (size_t)b * 32768 + (size_t)blockIdx.x * 8192;
    #pragma unroll
    for (int k = 0; k < 16; k++) {
        int p = tid + (k << 9);
        ((float4*)s)[p] = g4[p];
    }
    __syncthreads();
    // CRX chain: ctrl bit t+1 -> tgt bit t, t = 12..0  (wire = 14 - t)
    for (int t = 12; t >= 0; t--) {
        float2 cs = g_crx[layer][14 - t];
        unsigned m = (1u << t) - 1u;
        #pragma unroll
        for (int it = 0; it < 8; it++) {
            int p = tid + (it << 9);                   // 0..4095
            int i0 = ((p >> t) << (t + 2)) | (1 << (t + 1)) | (p & m);
            crxmix(s[i0], s[i0 | (1 << t)], cs.x, cs.y);
        }
        __syncthreads();
    }
    if (layer == 0) {
        // layer-2 single-qubit U on bits 13..1 (wires 2..14)
        for (int k = 13; k >= 1; k--) {
            const float2* gu = &g_U[1][b][15 - k][0];
            float2 u0 = gu[0], u1 = gu[1], u2 = gu[2], u3 = gu[3];
            unsigned m = (1u << k) - 1u;
            #pragma unroll
            for (int it = 0; it < 16; it++) {
                int p = tid + (it << 9);               // 0..8191
                int i0 = ((p >> k) << (k + 1)) | (p & m);
                umix(s[i0], s[i0 | (1 << k)], u0, u1, u2, u3);
            }
            __syncthreads();
        }
    }
    #pragma unroll
    for (int k = 0; k < 16; k++) {
        int p = tid + (k << 9);
        g4[p] = ((const float4*)s)[p];
    }
}

// ---------------- P3: boundary gates on bits {15,14,13,0} -------------------
__global__ __launch_bounds__(512) void k_boundary() {
    int b = blockIdx.y;
    int t = blockIdx.x * blockDim.x + threadIdx.x;   // 0..4095 : bits 1..12
    float4* g4 = g_state4 + (size_t)b * 32768;
    float2 r[2][2][2][2];                            // [b15][b14][b13][b0]
    #pragma unroll
    for (int b15 = 0; b15 < 2; b15++)
        #pragma unroll
        for (int b14 = 0; b14 < 2; b14++)
            #pragma unroll
            for (int b13 = 0; b13 < 2; b13++) {
                float4 v = g4[(b15 << 14) | (b14 << 13) | (b13 << 12) | t];
                r[b15][b14][b13][0] = make_float2(v.x, v.y);
                r[b15][b14][b13][1] = make_float2(v.z, v.w);
            }
    float2 cs = g_crx[0][15];                        // L1 wrap: ctrl b0 -> tgt b15
    #pragma unroll
    for (int b14 = 0; b14 < 2; b14++)
        #pragma unroll
        for (int b13 = 0; b13 < 2; b13++)
            crxmix(r[0][b14][b13][1], r[1][b14][b13][1], cs.x, cs.y);
    {   // L2 U wire 0 (bit 15)
        const float2* gu = &g_U[1][b][0][0];
        float2 u0 = gu[0], u1 = gu[1], u2 = gu[2], u3 = gu[3];
        #pragma unroll
        for (int i = 0; i < 8; i++)
            umix(r[0][(i >> 2) & 1][(i >> 1) & 1][i & 1],
                 r[1][(i >> 2) & 1][(i >> 1) & 1][i & 1], u0, u1, u2, u3);
    }
    {   // L2 U wire 1 (bit 14)
        const float2* gu = &g_U[1][b][1][0];
        float2 u0 = gu[0], u1 = gu[1], u2 = gu[2], u3 = gu[3];
        #pragma unroll
        for (int i = 0; i < 8; i++)
            umix(r[(i >> 2) & 1][0][(i >> 1) & 1][i & 1],
                 r[(i >> 2) & 1][1][(i >> 1) & 1][i & 1], u0, u1, u2, u3);
    }
    {   // L2 U wire 15 (bit 0)
        const float2* gu = &g_U[1][b][15][0];
        float2 u0 = gu[0], u1 = gu[1], u2 = gu[2], u3 = gu[3];
        #pragma unroll
        for (int i = 0; i < 8; i++)
            umix(r[(i >> 2) & 1][(i >> 1) & 1][i & 1][0],
                 r[(i >> 2) & 1][(i >> 1) & 1][i & 1][1], u0, u1, u2, u3);
    }
    cs = g_crx[1][0];                                // L2: ctrl b15 -> tgt b14
    #pragma unroll
    for (int b13 = 0; b13 < 2; b13++)
        #pragma unroll
        for (int b0 = 0; b0 < 2; b0++)
            crxmix(r[1][0][b13][b0], r[1][1][b13][b0], cs.x, cs.y);
    cs = g_crx[1][1];                                // L2: ctrl b14 -> tgt b13
    #pragma unroll
    for (int b15 = 0; b15 < 2; b15++)
        #pragma unroll
        for (int b0 = 0; b0 < 2; b0++)
            crxmix(r[b15][1][0][b0], r[b15][1][1][b0], cs.x, cs.y);
    #pragma unroll
    for (int b15 = 0; b15 < 2; b15++)
        #pragma unroll
        for (int b14 = 0; b14 < 2; b14++)
            #pragma unroll
            for (int b13 = 0; b13 < 2; b13++)
                g4[(b15 << 14) | (b14 << 13) | (b13 << 12) | t] =
                    make_float4(r[b15][b14][b13][0].x, r[b15][b14][b13][0].y,
                                r[b15][b14][b13][1].x, r[b15][b14][b13][1].y);
}

// ---------------- P5: final L2 wrap CRX + signed |amp|^2 reduction ----------
__global__ __launch_bounds__(256) void k_measure() {
    int b = blockIdx.y, blk = blockIdx.x, tid = threadIdx.x;
    const float2* st = (const float2*)g_state4 + (size_t)b * DIM;
    float2 cs = g_crx[1][15];                        // ctrl b0 -> tgt b15
    float sums[16];
    #pragma unroll
    for (int w = 0; w < 16; w++) sums[w] = 0.f;
    for (int k = 0; k < 16; k++) {
        int j = blk * 4096 + tid + k * 256;          // bits 0..14
        float2 a0 = st[j], a1 = st[j + 32768];
        if (j & 1) crxmix(a0, a1, cs.x, cs.y);
        float p0 = a0.x * a0.x + a0.y * a0.y;
        float p1 = a1.x * a1.x + a1.y * a1.y;
        sums[0] += p0 - p1;                          // wire 0 = bit 15
        #pragma unroll
        for (int w = 1; w < 16; w++) {
            float sp = p0 + p1;
            sums[w] += ((j >> (15 - w)) & 1) ? -sp : sp;
        }
    }
    __shared__ float sm[256][16];
    #pragma unroll
    for (int w = 0; w < 16; w++) sm[tid][w] = sums[w];
    __syncthreads();
    if (tid < 16) {
        float v = 0.f;
        for (int i = 0; i < 256; i++) v += sm[i][tid];
        g_partial[b][blk][tid] = v;
    }
}

// ---------------- P6: FC + log_softmax --------------------------------------
__global__ void k_head(const float* __restrict__ fc_w, const float* __restrict__ fc_b,
                       float* __restrict__ out) {
    int b = blockIdx.x, lane = threadIdx.x;
    __shared__ float feats[16];
    if (lane < 16) {
        float v = 0.f;
        #pragma unroll
        for (int k = 0; k < 8; k++) v += g_partial[b][k][lane];
        feats[lane] = v;
    }
    __syncthreads();
    float logit = -1e30f;
    if (lane < NC) {
        float v = fc_b[lane];
        #pragma unroll
        for (int w = 0; w < 16; w++) v += feats[w] * fc_w[lane * 16 + w];
        logit = v;
    }
    float m = logit;
    #pragma unroll
    for (int o = 16; o; o >>= 1) m = fmaxf(m, __shfl_xor_sync(0xffffffffu, m, o));
    float e = (lane < NC) ? expf(logit - m) : 0.f;
    #pragma unroll
    for (int o = 16; o; o >>= 1) e += __shfl_xor_sync(0xffffffffu, e, o);
    float lse = m + logf(e);
    if (lane < NC) out[b * NC + lane] = logit - lse;
}

extern "C" void kernel_launch(void* const* d_in, const int* in_sizes, int n_in,
                              void* d_out, int out_size) {
    const float* x    = (const float*)d_in[0];
    const float* w0   = (const float*)d_in[1];
    const float* x0   = (const float*)d_in[2];
    const float* w1   = (const float*)d_in[3];
    const float* x1   = (const float*)d_in[4];
    const float* fc_w = (const float*)d_in[5];
    const float* fc_b = (const float*)d_in[6];
    float* out = (float*)d_out;

    cudaFuncSetAttribute(k_chain, cudaFuncAttributeMaxDynamicSharedMemorySize, 131072);

    k_prep<<<8, 256>>>(x, w0, x0, w1, x1);
    k_init<<<dim3(16, BATCH), 512>>>();
    k_chain<<<dim3(4, BATCH), 512, 131072>>>(0);
    k_boundary<<<dim3(8, BATCH), 512>>>();
    k_chain<<<dim3(4, BATCH), 512, 131072>>>(1);
    k_measure<<<dim3(8, BATCH), 256>>>();
    k_head<<<BATCH, 32>>>(fc_w, fc_b, out);
}

// round 4
// speedup vs baseline: 1.6006x; 1.6006x over previous
#include <cuda_runtime.h>
#include <math.h>

#define NQ 16
#define DIM 65536
#define BATCH 64
#define NC 23

__device__ float4 g_state4[BATCH * DIM / 2];   // 32 MB state
__device__ float2 g_U[2][BATCH][NQ][4];        // fused Rot@RX per layer/sample/wire
__device__ float2 g_crx[2][NQ];                // (cos(th/2), sin(th/2))
__device__ float  g_partial[BATCH][8][16];

// smem pad: conflict-free for all window strides (verified per half-warp)
#define PD(i) ((i) + ((i) >> 4))
#define SMEM_F2 8704                            // 8192 + 512 pad
#define SMEM_BYTES (SMEM_F2 * 8)

__device__ __forceinline__ float2 cmul(float2 a, float2 b) {
    return make_float2(a.x * b.x - a.y * b.y, a.x * b.y + a.y * b.x);
}
__device__ __forceinline__ void umix(float2& a0, float2& a1,
                                     float2 u0, float2 u1, float2 u2, float2 u3) {
    float2 n0, n1;
    n0.x = u0.x * a0.x - u0.y * a0.y + u1.x * a1.x - u1.y * a1.y;
    n0.y = u0.x * a0.y + u0.y * a0.x + u1.x * a1.y + u1.y * a1.x;
    n1.x = u2.x * a0.x - u2.y * a0.y + u3.x * a1.x - u3.y * a1.y;
    n1.y = u2.x * a0.y + u2.y * a0.x + u3.x * a1.y + u3.y * a1.x;
    a0 = n0; a1 = n1;
}
// RX pair mix applied under control=1: RX=[[c,-is],[-is,c]]
__device__ __forceinline__ void crxmix(float2& a0, float2& a1, float c, float s) {
    float2 n0 = make_float2(c * a0.x + s * a1.y, c * a0.y - s * a1.x);
    float2 n1 = make_float2(s * a0.y + c * a1.x, -s * a0.x + c * a1.y);
    a0 = n0; a1 = n1;
}

// ---------------- P0: fused U = Rot @ RX, CRX tables ------------------------
__global__ void k_prep(const float* __restrict__ x, const float* __restrict__ w0,
                       const float* __restrict__ x0, const float* __restrict__ w1,
                       const float* __restrict__ x1) {
    int t = blockIdx.x * blockDim.x + threadIdx.x;
    if (t < 2 * NQ) {
        int l = t >> 4, q = t & 15;
        float th = 0.5f * (l == 0 ? x0[q] : x1[q]);
        g_crx[l][q] = make_float2(cosf(th), sinf(th));
    }
    if (t < 2 * BATCH * NQ) {
        int l = t / (BATCH * NQ);
        int r = t % (BATCH * NQ);
        int b = r / NQ, q = r % NQ;
        float hx = 0.5f * x[b * NQ + q];
        float cx = cosf(hx), sx = sinf(hx);
        const float* w = (l == 0 ? w0 : w1) + q * 3;
        float phi = w[0], th = w[1], om = w[2];
        float ct = cosf(0.5f * th), st = sinf(0.5f * th);
        float ap = 0.5f * (phi + om), am = 0.5f * (phi - om);
        float cap = cosf(ap), sap = sinf(ap), cam = cosf(am), sam = sinf(am);
        float2 a  = make_float2(cap * ct, -sap * ct);
        float2 bb = make_float2(-cam * st, -sam * st);
        float2 cc = make_float2(cam * st, -sam * st);
        float2 d  = make_float2(cap * ct,  sap * ct);
        g_U[l][b][q][0] = make_float2(a.x * cx + bb.y * sx,  a.y * cx - bb.x * sx);
        g_U[l][b][q][1] = make_float2(a.y * sx + bb.x * cx, -a.x * sx + bb.y * cx);
        g_U[l][b][q][2] = make_float2(cc.x * cx + d.y * sx,  cc.y * cx - d.x * sx);
        g_U[l][b][q][3] = make_float2(cc.y * sx + d.x * cx, -cc.x * sx + d.y * cx);
    }
}

// ------- P1: product state + L1 CRX q0 (b15->b14), q1 (b14->b13), q2 (b13->b12)
__global__ __launch_bounds__(512) void k_init() {
    int b = blockIdx.y;
    int t = blockIdx.x * blockDim.x + threadIdx.x;   // 0..4095 : bits 0..11
    __shared__ float2 f[16][2];
    if (threadIdx.x < 32) {
        int j = threadIdx.x >> 1, v = threadIdx.x & 1;
        f[j][v] = g_U[0][b][15 - j][v * 2];          // column 0 of U, wire 15-j
    }
    __syncthreads();
    float2 c = f[0][t & 1];
    #pragma unroll
    for (int j = 1; j <= 11; j++) c = cmul(c, f[j][(t >> j) & 1]);
    // a[i], i = (b15<<3)|(b14<<2)|(b13<<1)|b12
    float2 t12[2], t13[4], t14[8], a[16];
    t12[0] = cmul(c, f[12][0]); t12[1] = cmul(c, f[12][1]);
    #pragma unroll
    for (int i = 0; i < 2; i++) { t13[i] = cmul(t12[i], f[13][0]); t13[i + 2] = cmul(t12[i], f[13][1]); }
    #pragma unroll
    for (int i = 0; i < 4; i++) { t14[i] = cmul(t13[i], f[14][0]); t14[i + 4] = cmul(t13[i], f[14][1]); }
    #pragma unroll
    for (int i = 0; i < 8; i++) { a[i] = cmul(t14[i], f[15][0]); a[i + 8] = cmul(t14[i], f[15][1]); }
    float2 cs = g_crx[0][0];                         // ctrl b15 -> tgt b14
    #pragma unroll
    for (int i = 8; i < 12; i++) crxmix(a[i], a[i | 4], cs.x, cs.y);
    cs = g_crx[0][1];                                // ctrl b14 -> tgt b13
    crxmix(a[4], a[6], cs.x, cs.y);  crxmix(a[5], a[7], cs.x, cs.y);
    crxmix(a[12], a[14], cs.x, cs.y); crxmix(a[13], a[15], cs.x, cs.y);
    cs = g_crx[0][2];                                // ctrl b13 -> tgt b12
    crxmix(a[2], a[3], cs.x, cs.y);  crxmix(a[6], a[7], cs.x, cs.y);
    crxmix(a[10], a[11], cs.x, cs.y); crxmix(a[14], a[15], cs.x, cs.y);
    float2* st = (float2*)g_state4 + (size_t)b * DIM;
    #pragma unroll
    for (int i = 0; i < 16; i++) st[(i << 12) | t] = a[i];
}

// ---------------- window gate helpers ----------------------------------------
template<int H, int L>
__device__ __forceinline__ void applyCRX(float2* r, float2 cs) {
    #pragma unroll
    for (int j = 0; j < 16; j++)
        if (((j >> H) & 1) && !((j >> L) & 1))
            crxmix(r[j], r[j | (1 << L)], cs.x, cs.y);
}
template<int K>
__device__ __forceinline__ void applyU(float2* r, const float2* __restrict__ gu) {
    float2 u0 = gu[0], u1 = gu[1], u2 = gu[2], u3 = gu[3];
    #pragma unroll
    for (int j = 0; j < 16; j++)
        if (!((j >> K) & 1))
            umix(r[j], r[j | (1 << K)], u0, u1, u2, u3);
}

// one 4-bit window pass over bits [sh, sh+3] of the 8192-amp chunk in smem.
// CRX gates q = 12-sh, 13-sh, 14-sh; if DOU also L2 U wires 12-sh,13-sh,14-sh.
__device__ __forceinline__ void window_pass(float2* s, int tid, int b, int sh, bool dou, int layer) {
    int low  = tid & ((1 << sh) - 1);
    int base = ((tid >> sh) << (sh + 4)) | low;
    float2 r[16];
    #pragma unroll
    for (int j = 0; j < 16; j++) r[j] = s[PD(base + (j << sh))];
    applyCRX<3, 2>(r, g_crx[layer][12 - sh]);
    applyCRX<2, 1>(r, g_crx[layer][13 - sh]);
    applyCRX<1, 0>(r, g_crx[layer][14 - sh]);
    if (dou) {
        applyU<3>(r, &g_U[1][b][12 - sh][0]);
        applyU<2>(r, &g_U[1][b][13 - sh][0]);
        applyU<1>(r, &g_U[1][b][14 - sh][0]);
    }
    #pragma unroll
    for (int j = 0; j < 16; j++) s[PD(base + (j << sh))] = r[j];
}

// ------- P2/P4: 64KB chunk (bits 0..12), 4 window passes ---------------------
// layer 0: L1 CRX q=3..14 + L2 U wires 3..14 folded in.  layer 1: L2 CRX q=3..14.
__global__ __launch_bounds__(512) void k_chain(int layer) {
    extern __shared__ float2 s[];
    int b = blockIdx.y, tid = threadIdx.x;
    float2* g = (float2*)g_state4 + (size_t)b * DIM + (size_t)blockIdx.x * 8192;
    bool dou = (layer == 0);
    #pragma unroll
    for (int k = 0; k < 16; k++) {
        int p = tid + (k << 9);
        s[PD(p)] = g[p];
    }
    __syncthreads();
    window_pass(s, tid, b, 9, dou, layer); __syncthreads();
    window_pass(s, tid, b, 6, dou, layer); __syncthreads();
    window_pass(s, tid, b, 3, dou, layer); __syncthreads();
    window_pass(s, tid, b, 0, dou, layer); __syncthreads();
    #pragma unroll
    for (int k = 0; k < 16; k++) {
        int p = tid + (k << 9);
        g[p] = s[PD(p)];
    }
}

// ------- P3: boundary gates on bits {15,14,13,12,0} --------------------------
// L1 wrap q15; L2 U wires 0,1,2,15; L2 CRX q0,q1,q2.
__global__ __launch_bounds__(256) void k_boundary() {
    int b = blockIdx.y;
    int t = blockIdx.x * blockDim.x + threadIdx.x;   // 0..2047 : f2 bits 1..11
    float4* g4 = g_state4 + (size_t)b * 32768;
    float2 r[16][2];                                 // [i=(b15<<3)|(b14<<2)|(b13<<1)|b12][b0]
    #pragma unroll
    for (int i = 0; i < 16; i++) {
        float4 v = g4[(i << 11) | t];
        r[i][0] = make_float2(v.x, v.y);
        r[i][1] = make_float2(v.z, v.w);
    }
    {   // L1 wrap: ctrl b0 -> tgt b15
        float2 cs = g_crx[0][15];
        #pragma unroll
        for (int i = 0; i < 8; i++) crxmix(r[i][1], r[i + 8][1], cs.x, cs.y);
    }
    {   // L2 U wire 0 (bit 15)
        const float2* gu = &g_U[1][b][0][0];
        float2 u0 = gu[0], u1 = gu[1], u2 = gu[2], u3 = gu[3];
        #pragma unroll
        for (int i = 0; i < 8; i++) {
            umix(r[i][0], r[i + 8][0], u0, u1, u2, u3);
            umix(r[i][1], r[i + 8][1], u0, u1, u2, u3);
        }
    }
    {   // L2 U wire 1 (bit 14)
        const float2* gu = &g_U[1][b][1][0];
        float2 u0 = gu[0], u1 = gu[1], u2 = gu[2], u3 = gu[3];
        #pragma unroll
        for (int i = 0; i < 16; i++)
            if (!((i >> 2) & 1)) {
                umix(r[i][0], r[i + 4][0], u0, u1, u2, u3);
                umix(r[i][1], r[i + 4][1], u0, u1, u2, u3);
            }
    }
    {   // L2 U wire 2 (bit 13)
        const float2* gu = &g_U[1][b][2][0];
        float2 u0 = gu[0], u1 = gu[1], u2 = gu[2], u3 = gu[3];
        #pragma unroll
        for (int i = 0; i < 16; i++)
            if (!((i >> 1) & 1)) {
                umix(r[i][0], r[i + 2][0], u0, u1, u2, u3);
                umix(r[i][1], r[i + 2][1], u0, u1, u2, u3);
            }
    }
    {   // L2 U wire 15 (bit 0)
        const float2* gu = &g_U[1][b][15][0];
        float2 u0 = gu[0], u1 = gu[1], u2 = gu[2], u3 = gu[3];
        #pragma unroll
        for (int i = 0; i < 16; i++)
            umix(r[i][0], r[i][1], u0, u1, u2, u3);
    }
    {   // L2 q0: ctrl b15 -> tgt b14
        float2 cs = g_crx[1][0];
        #pragma unroll
        for (int i = 8; i < 12; i++) {
            crxmix(r[i][0], r[i + 4][0], cs.x, cs.y);
            crxmix(r[i][1], r[i + 4][1], cs.x, cs.y);
        }
    }
    {   // L2 q1: ctrl b14 -> tgt b13
        float2 cs = g_crx[1][1];
        #pragma unroll
        for (int i = 0; i < 16; i++)
            if (((i >> 2) & 1) && !((i >> 1) & 1)) {
                crxmix(r[i][0], r[i + 2][0], cs.x, cs.y);
                crxmix(r[i][1], r[i + 2][1], cs.x, cs.y);
            }
    }
    {   // L2 q2: ctrl b13 -> tgt b12
        float2 cs = g_crx[1][2];
        #pragma unroll
        for (int i = 0; i < 16; i++)
            if (((i >> 1) & 1) && !(i & 1)) {
                crxmix(r[i][0], r[i + 1][0], cs.x, cs.y);
                crxmix(r[i][1], r[i + 1][1], cs.x, cs.y);
            }
    }
    #pragma unroll
    for (int i = 0; i < 16; i++)
        g4[(i << 11) | t] = make_float4(r[i][0].x, r[i][0].y, r[i][1].x, r[i][1].y);
}

// ------- P5: final L2 wrap CRX (q15: b0->b15) + signed |amp|^2 reduction -----
__global__ __launch_bounds__(256) void k_measure() {
    int b = blockIdx.y, blk = blockIdx.x, tid = threadIdx.x;
    const float4* st4 = g_state4 + (size_t)b * 32768;
    float2 cs = g_crx[1][15];
    float sums[16];
    #pragma unroll
    for (int w = 0; w < 16; w++) sums[w] = 0.f;
    #pragma unroll
    for (int k = 0; k < 8; k++) {
        int f = blk * 2048 + tid + k * 256;          // f4 idx: f2 bits 1..14
        float4 lo = st4[f], hi = st4[f + 16384];
        float2 a0e = make_float2(lo.x, lo.y), a0o = make_float2(lo.z, lo.w);
        float2 a1e = make_float2(hi.x, hi.y), a1o = make_float2(hi.z, hi.w);
        crxmix(a0o, a1o, cs.x, cs.y);                // wrap only where bit0=1
        float p0e = a0e.x * a0e.x + a0e.y * a0e.y;
        float p1e = a1e.x * a1e.x + a1e.y * a1e.y;
        float p0o = a0o.x * a0o.x + a0o.y * a0o.y;
        float p1o = a1o.x * a1o.x + a1o.y * a1o.y;
        int j = f << 1;                              // even index; odd = j|1
        sums[0] += (p0e - p1e) + (p0o - p1o);        // wire 0 = bit 15
        float se = p0e + p1e, so = p0o + p1o;
        float sall = se + so;
        #pragma unroll
        for (int w = 1; w < 15; w++)
            sums[w] += ((j >> (15 - w)) & 1) ? -sall : sall;
        sums[15] += se - so;                         // wire 15 = bit 0
    }
    __shared__ float sm[256][16];
    #pragma unroll
    for (int w = 0; w < 16; w++) sm[tid][w] = sums[w];
    __syncthreads();
    if (tid < 16) {
        float v = 0.f;
        for (int i = 0; i < 256; i++) v += sm[i][tid];
        g_partial[b][blk][tid] = v;
    }
}

// ---------------- P6: FC + log_softmax --------------------------------------
__global__ void k_head(const float* __restrict__ fc_w, const float* __restrict__ fc_b,
                       float* __restrict__ out) {
    int b = blockIdx.x, lane = threadIdx.x;
    __shared__ float feats[16];
    if (lane < 16) {
        float v = 0.f;
        #pragma unroll
        for (int k = 0; k < 8; k++) v += g_partial[b][k][lane];
        feats[lane] = v;
    }
    __syncthreads();
    float logit = -1e30f;
    if (lane < NC) {
        float v = fc_b[lane];
        #pragma unroll
        for (int w = 0; w < 16; w++) v += feats[w] * fc_w[lane * 16 + w];
        logit = v;
    }
    float m = logit;
    #pragma unroll
    for (int o = 16; o; o >>= 1) m = fmaxf(m, __shfl_xor_sync(0xffffffffu, m, o));
    float e = (lane < NC) ? expf(logit - m) : 0.f;
    #pragma unroll
    for (int o = 16; o; o >>= 1) e += __shfl_xor_sync(0xffffffffu, e, o);
    float lse = m + logf(e);
    if (lane < NC) out[b * NC + lane] = logit - lse;
}

extern "C" void kernel_launch(void* const* d_in, const int* in_sizes, int n_in,
                              void* d_out, int out_size) {
    const float* x    = (const float*)d_in[0];
    const float* w0   = (const float*)d_in[1];
    const float* x0   = (const float*)d_in[2];
    const float* w1   = (const float*)d_in[3];
    const float* x1   = (const float*)d_in[4];
    const float* fc_w = (const float*)d_in[5];
    const float* fc_b = (const float*)d_in[6];
    float* out = (float*)d_out;

    cudaFuncSetAttribute(k_chain, cudaFuncAttributeMaxDynamicSharedMemorySize, SMEM_BYTES);

    k_prep<<<8, 256>>>(x, w0, x0, w1, x1);
    k_init<<<dim3(8, BATCH), 512>>>();
    k_chain<<<dim3(8, BATCH), 512, SMEM_BYTES>>>(0);
    k_boundary<<<dim3(8, BATCH), 256>>>();
    k_chain<<<dim3(8, BATCH), 512, SMEM_BYTES>>>(1);
    k_measure<<<dim3(8, BATCH), 256>>>();
    k_head<<<BATCH, 32>>>(fc_w, fc_b, out);
}